// round 13
// baseline (speedup 1.0000x reference)
#include <cuda_runtime.h>
#include <cstdint>

#define Bn 64
#define Tn 512
#define In 128
#define Hn 512
#define TnHn (Tn*Hn)
#define BTH (64*512*512)

// 64MB scratch for precomputed v_in = x @ W_in^T + b_in, layout [B*T, H]
__device__ float g_vin[BTH];

__device__ __forceinline__ uint32_t smem_u32(const void* p) {
    return (uint32_t)__cvta_generic_to_shared(p);
}

// Packed fp32x2 FMA (Blackwell FFMA2): d = a*b + d on both lanes, exact fp32.
__device__ __forceinline__ void ffma2(unsigned long long& d,
                                      unsigned long long a,
                                      unsigned long long b) {
    asm("fma.rn.f32x2 %0, %1, %2, %0;" : "+l"(d) : "l"(a), "l"(b));
}
__device__ __forceinline__ float hsum2(unsigned long long a) {
    float lo, hi;
    asm("mov.b64 {%0, %1}, %2;" : "=f"(lo), "=f"(hi) : "l"(a));
    return lo + hi;
}

__device__ __forceinline__ void mbar_init(uint32_t mbar, uint32_t cnt) {
    asm volatile("mbarrier.init.shared.b64 [%0], %1;" :: "r"(mbar), "r"(cnt) : "memory");
}
__device__ __forceinline__ void mbar_expect_tx(uint32_t mbar, uint32_t bytes) {
    asm volatile("mbarrier.arrive.expect_tx.shared.b64 _, [%0], %1;"
                 :: "r"(mbar), "r"(bytes) : "memory");
}
__device__ __forceinline__ void mbar_wait(uint32_t mbar, uint32_t parity) {
    asm volatile(
        "{\n\t.reg .pred P;\n\t"
        "WL_%=:\n\t"
        "mbarrier.try_wait.parity.acquire.cta.shared::cta.b64 P, [%0], %1, 0x989680;\n\t"
        "@!P bra WL_%=;\n\t}"
        :: "r"(mbar), "r"(parity) : "memory");
}
__device__ __forceinline__ uint32_t mapa_rk(uint32_t la, int rk) {
    uint32_t ra;
    asm("mapa.shared::cluster.u32 %0, %1, %2;" : "=r"(ra) : "r"(la), "r"(rk));
    return ra;
}
// Remote smem store that also delivers complete_tx to the remote mbarrier.
__device__ __forceinline__ void st_async_f32(uint32_t raddr, float v, uint32_t rmbar) {
    asm volatile("st.async.shared::cluster.mbarrier::complete_tx::bytes.f32 [%0], %1, [%2];"
                 :: "r"(raddr), "f"(v), "r"(rmbar) : "memory");
}

// ---------------------------------------------------------------------------
// Kernel 1: v_in GEMM.  g_vin[bt][h] = b_in[h] + sum_i x[bt][i] * W_in[h][i]
// ---------------------------------------------------------------------------
#define VIN_SMEM (2*128*132*4)

__global__ __launch_bounds__(256, 1)
void vin_gemm_kernel(const float* __restrict__ x,
                     const float* __restrict__ W_in,
                     const float* __restrict__ b_in) {
    extern __shared__ float sm[];
    float* xs = sm;             // [128 bt][132]
    float* ws = sm + 128*132;   // [128 k][132]

    const int row0 = blockIdx.x * 128;
    const int h0   = blockIdx.y * 128;

    for (int idx = threadIdx.x; idx < 128*32; idx += 256) {
        int r = idx >> 5, c4 = idx & 31;
        float4 v = *(const float4*)(x + (size_t)(row0 + r)*In + c4*4);
        *(float4*)(xs + r*132 + c4*4) = v;
        float4 w = *(const float4*)(W_in + (size_t)(h0 + r)*In + c4*4);
        ws[(c4*4 + 0)*132 + r] = w.x;
        ws[(c4*4 + 1)*132 + r] = w.y;
        ws[(c4*4 + 2)*132 + r] = w.z;
        ws[(c4*4 + 3)*132 + r] = w.w;
    }
    __syncthreads();

    const int ty = threadIdx.x >> 4;
    const int tx = threadIdx.x & 15;
    const int rb = ty * 8;
    const int cb = tx * 8;

    float acc[8][8];
    #pragma unroll
    for (int i = 0; i < 8; i++)
        #pragma unroll
        for (int j = 0; j < 8; j++) acc[i][j] = 0.f;

    #pragma unroll 2
    for (int k = 0; k < 128; ++k) {
        float a[8];
        #pragma unroll
        for (int i = 0; i < 8; i++) a[i] = xs[(rb + i)*132 + k];
        float bb[8];
        *(float4*)(bb)     = *(const float4*)(ws + k*132 + cb);
        *(float4*)(bb + 4) = *(const float4*)(ws + k*132 + cb + 4);
        #pragma unroll
        for (int i = 0; i < 8; i++) {
            float av = a[i];
            #pragma unroll
            for (int j = 0; j < 8; j++) acc[i][j] = fmaf(av, bb[j], acc[i][j]);
        }
    }

    float bias[8];
    *(float4*)(bias)     = *(const float4*)(b_in + h0 + cb);
    *(float4*)(bias + 4) = *(const float4*)(b_in + h0 + cb + 4);

    #pragma unroll
    for (int i = 0; i < 8; i++) {
        float* orow = g_vin + (size_t)(row0 + rb + i)*Hn + h0 + cb;
        float4 o0, o1;
        o0.x = acc[i][0] + bias[0]; o0.y = acc[i][1] + bias[1];
        o0.z = acc[i][2] + bias[2]; o0.w = acc[i][3] + bias[3];
        o1.x = acc[i][4] + bias[4]; o1.y = acc[i][5] + bias[5];
        o1.z = acc[i][6] + bias[6]; o1.w = acc[i][7] + bias[7];
        *(float4*)(orow)     = o0;
        *(float4*)(orow + 4) = o1;
    }
}

// ---------------------------------------------------------------------------
// Kernel 2: recurrence, ONE phase per timestep.
// 16 clusters x 8 CTAs, 512 thr. Thread = (h = tid>>3, seg = tid&7):
// W_hid row (rank*64+h), cols [seg*64,+64) in regs; j-loop covers all 4
// batches (128 FFMA2). Seg reduction = 3x shfl_xor in the 8-lane group; all
// lanes replicate the elementwise update bitwise-identically; lane 'seg'
// fans out the 4 batch values to rank==seg (4 st.async) and writes one
// output float (seg selects (array,batch)). One mbar wait + one
// __syncthreads per step (sync also orders the tid0 expect_tx re-arm before
// any thread's fan-out stores). Slots: read t&1, write (t+1)&1; expected tx
// per slot per phase = 8 ranks * 64 h * 4 b * 4 B = 8192 B.
// 'last' (skip v_in prefetch) is asserted ONLY at t=511 where t+1 would be
// out of bounds — R11's bug was asserting it at t=510, leaving the epilogue
// step with stale v_in.
// fr layout per slot: [4 b][8 seg][68] (pad => conflict-free LDS.128).
// ---------------------------------------------------------------------------
#define SEGW  68
#define SLOTF (4*8*SEGW)            // 2176 floats per slot
#define MB_OFF (2*SLOTF*4)
#define REC_SMEM (MB_OFF + 64)
#define TXB 8192u

struct RState {
    float v[4], vin[4];
    unsigned ovin[4];     // g_vin index for current t, per batch
    unsigned myot;        // out index for my (arr,b2) stream at current t
    int arr, b2;
};

template<bool SIG>
__device__ __forceinline__ void step_body(
    const float* __restrict__ rbase,       // read slot base
    const uint32_t* __restrict__ wdst,     // 4 remote fr addrs (write slot)
    uint32_t sig,                          // remote mbar for write slot
    const ulonglong2* __restrict__ w,
    int seg, float al, float oma, float bias,
    RState& S, float* __restrict__ out, bool last)
{
    // j-loop: 4 batches x 64 j (this thread's segment)
    unsigned long long ae[4] = {0ull,0ull,0ull,0ull};
    unsigned long long ao[4] = {0ull,0ull,0ull,0ull};
    #pragma unroll
    for (int i = 0; i < 16; i++) {
        const ulonglong2 wi = w[i];
        #pragma unroll
        for (int b = 0; b < 4; b++) {
            ulonglong2 f = *(const ulonglong2*)(rbase + (b*8 + seg)*SEGW + i*4);
            ffma2(ae[b], wi.x, f.x);
            ffma2(ao[b], wi.y, f.y);
        }
    }
    float s0 = hsum2(ae[0]) + hsum2(ao[0]);
    float s1 = hsum2(ae[1]) + hsum2(ao[1]);
    float s2 = hsum2(ae[2]) + hsum2(ao[2]);
    float s3 = hsum2(ae[3]) + hsum2(ao[3]);
    #pragma unroll
    for (int m = 1; m < 8; m <<= 1) {
        s0 += __shfl_xor_sync(0xffffffffu, s0, m);
        s1 += __shfl_xor_sync(0xffffffffu, s1, m);
        s2 += __shfl_xor_sync(0xffffffffu, s2, m);
        s3 += __shfl_xor_sync(0xffffffffu, s3, m);
    }
    float vh[4] = { s0 + bias, s1 + bias, s2 + bias, s3 + bias };
    float fn[4], fr_r[4];
    #pragma unroll
    for (int b = 0; b < 4; b++) {
        float vn = oma*S.v[b] + al*(vh[b] + S.vin[b]);
        float vr = oma*vn + al*vh[b];
        S.v[b] = vn;
        fn[b]   = fmaxf(vn, 0.f);
        fr_r[b] = fmaxf(vr, 0.f);
    }
    if (SIG) {
        #pragma unroll
        for (int b = 0; b < 4; b++) st_async_f32(wdst[b], fn[b], sig);
    }
    // one output float per thread: arr=seg>>2 selects states/relax, b2=seg&3
    out[S.myot] = S.arr ? fr_r[S.b2] : fn[S.b2];
    S.myot += Hn;
    if (!last) {
        #pragma unroll
        for (int b = 0; b < 4; b++) {
            S.ovin[b] += Hn;
            S.vin[b] = __ldg(g_vin + S.ovin[b]);
        }
    }
}

__global__ __launch_bounds__(512, 1) __cluster_dims__(8, 1, 1)
void recur_kernel(const float* __restrict__ init_state,
                  const float* __restrict__ W_hid,
                  const float* __restrict__ b_hid,
                  const float* __restrict__ alpha,
                  float* __restrict__ out) {
    extern __shared__ float sm[];
    float* fr0 = sm;             // slot0: [4][8][68]
    float* fr1 = sm + SLOTF;

    const int tid  = threadIdx.x;
    const int rank = blockIdx.x;      // cluster rank -> h slice
    const int clu  = blockIdx.y;
    const int hl   = tid >> 3;        // 0..63
    const int seg  = tid & 7;         // j segment AND fan-out dest rank

    const uint32_t smb = smem_u32(sm);
    const uint32_t mb0 = smb + MB_OFF;
    const uint32_t mb1 = mb0 + 8;

    // ---- W_hid slice into regs (row rank*64+hl, cols seg*64..+64) ----
    ulonglong2 w[16];
    {
        const float* wr = W_hid + (size_t)(rank*64 + hl)*Hn + seg*64;
        #pragma unroll
        for (int i = 0; i < 16; i++)
            w[i] = *(const ulonglong2*)(wr + i*4);
    }

    // ---- fill slot0 with relu(init_state) for this cluster's 4 batches ----
    for (int idx = tid; idx < 4*512; idx += 512) {
        int b = idx >> 9, j = idx & 511;
        float s = fmaxf(init_state[(size_t)(clu*4 + b)*Hn + j], 0.f);
        fr0[(b*8 + (j >> 6))*SEGW + (j & 63)] = s;
    }

    // ---- mbarrier init + prologue arm ----
    if (tid == 0) {
        mbar_init(mb0, 1); mbar_init(mb1, 1);
        asm volatile("fence.mbarrier_init.release.cluster;" ::: "memory");
        mbar_expect_tx(mb0, TXB);
        mbar_expect_tx(mb1, TXB);
    }

    // ---- per-thread state ----
    const int hg = rank*64 + hl;
    const float al   = alpha[hg];
    const float oma  = 1.f - al;
    const float bias = b_hid[hg];
    RState S;
    S.arr = seg >> 2;
    S.b2  = seg & 3;
    #pragma unroll
    for (int b = 0; b < 4; b++) {
        const int bg = clu*4 + b;
        S.v[b]    = init_state[(size_t)bg*Hn + hg];
        S.ovin[b] = (unsigned)(bg*TnHn + hg);
        S.vin[b]  = __ldg(g_vin + S.ovin[b]);
    }
    S.myot = (unsigned)(S.arr*BTH) + (unsigned)((clu*4 + S.b2)*TnHn + hg);

    // ---- loop-invariant remote addresses: (hl, b) -> dest rank=seg,
    //      dest offset fr[slot][b][rank][hl] ----
    uint32_t wdst0[4], wdst1[4];
    #pragma unroll
    for (int b = 0; b < 4; b++) {
        uint32_t off = (uint32_t)((b*8 + rank)*SEGW + hl) * 4u;
        wdst0[b] = mapa_rk(smb + off,            seg);
        wdst1[b] = mapa_rk(smb + SLOTF*4u + off, seg);
    }
    const uint32_t sig0 = mapa_rk(mb0, seg);
    const uint32_t sig1 = mapa_rk(mb1, seg);

    __syncthreads();
    asm volatile("barrier.cluster.arrive.aligned;" ::: "memory");
    asm volatile("barrier.cluster.wait.aligned;"   ::: "memory");

    // ---- t = 0: read slot0 (prologue-filled), write slot1 ----
    step_body<true>(fr0, wdst1, sig1, w, seg, al, oma, bias, S, out, false);

    // ---- t = 2u+1 (odd: read slot1, write slot0), t = 2u+2 (even) ----
    #pragma unroll 1
    for (int u = 0; u < 255; ++u) {
        const uint32_t par = (uint32_t)(u & 1);
        mbar_wait(mb1, par);
        if (tid == 0) mbar_expect_tx(mb1, TXB);
        __syncthreads();
        step_body<true>(fr1, wdst0, sig0, w, seg, al, oma, bias, S, out, false);

        mbar_wait(mb0, par);
        if (tid == 0) mbar_expect_tx(mb0, TXB);
        __syncthreads();
        // NOTE: prefetch of v_in[t+1] stays ON here (even at t=510; index is
        // in bounds). Only t=511 itself skips the prefetch.
        step_body<true>(fr0, wdst1, sig1, w, seg, al, oma, bias, S, out, false);
    }

    // ---- t = 511: read slot1, no fan-out, no prefetch (t+1 == Tn) ----
    mbar_wait(mb1, 1u);
    __syncthreads();
    step_body<false>(fr1, wdst0, sig0, w, seg, al, oma, bias, S, out, true);

    // No CTA may exit while a peer could still have remote stores in flight
    // toward its smem (exit deallocates smem -> fault).
    asm volatile("barrier.cluster.arrive.aligned;" ::: "memory");
    asm volatile("barrier.cluster.wait.aligned;"   ::: "memory");
}

// ---------------------------------------------------------------------------
extern "C" void kernel_launch(void* const* d_in, const int* in_sizes, int n_in,
                              void* d_out, int out_size) {
    const float* x          = (const float*)d_in[0];
    const float* init_state = (const float*)d_in[1];
    const float* W_in       = (const float*)d_in[2];
    const float* b_in       = (const float*)d_in[3];
    const float* W_hid      = (const float*)d_in[4];
    const float* b_hid      = (const float*)d_in[5];
    const float* alpha      = (const float*)d_in[6];
    float* out = (float*)d_out;

    cudaFuncSetAttribute(vin_gemm_kernel,
                         cudaFuncAttributeMaxDynamicSharedMemorySize, VIN_SMEM);
    cudaFuncSetAttribute(recur_kernel,
                         cudaFuncAttributeMaxDynamicSharedMemorySize, REC_SMEM);

    vin_gemm_kernel<<<dim3(Bn*Tn/128, Hn/128), 256, VIN_SMEM>>>(x, W_in, b_in);
    recur_kernel<<<dim3(8, Bn/4), 512, REC_SMEM>>>(init_state, W_hid, b_hid,
                                                   alpha, out);
}

// round 14
// speedup vs baseline: 1.0258x; 1.0258x over previous
#include <cuda_runtime.h>
#include <cstdint>

#define Bn 64
#define Tn 512
#define In 128
#define Hn 512
#define TnHn (Tn*Hn)
#define BTH (64*512*512)

// 64MB scratch for precomputed v_in = x @ W_in^T + b_in, layout [B*T, H]
__device__ float g_vin[BTH];

__device__ __forceinline__ uint32_t smem_u32(const void* p) {
    return (uint32_t)__cvta_generic_to_shared(p);
}

// Packed fp32x2 FMA (Blackwell FFMA2): d = a*b + d on both lanes, exact fp32.
__device__ __forceinline__ void ffma2(unsigned long long& d,
                                      unsigned long long a,
                                      unsigned long long b) {
    asm("fma.rn.f32x2 %0, %1, %2, %0;" : "+l"(d) : "l"(a), "l"(b));
}
__device__ __forceinline__ float hsum2(unsigned long long a) {
    float lo, hi;
    asm("mov.b64 {%0, %1}, %2;" : "=f"(lo), "=f"(hi) : "l"(a));
    return lo + hi;
}

__device__ __forceinline__ void mbar_init(uint32_t mbar, uint32_t cnt) {
    asm volatile("mbarrier.init.shared.b64 [%0], %1;" :: "r"(mbar), "r"(cnt) : "memory");
}
__device__ __forceinline__ void mbar_expect_tx(uint32_t mbar, uint32_t bytes) {
    asm volatile("mbarrier.arrive.expect_tx.shared.b64 _, [%0], %1;"
                 :: "r"(mbar), "r"(bytes) : "memory");
}
__device__ __forceinline__ void mbar_wait(uint32_t mbar, uint32_t parity) {
    asm volatile(
        "{\n\t.reg .pred P;\n\t"
        "WL_%=:\n\t"
        "mbarrier.try_wait.parity.acquire.cta.shared::cta.b64 P, [%0], %1, 0x989680;\n\t"
        "@!P bra WL_%=;\n\t}"
        :: "r"(mbar), "r"(parity) : "memory");
}
__device__ __forceinline__ uint32_t mapa_rk(uint32_t la, int rk) {
    uint32_t ra;
    asm("mapa.shared::cluster.u32 %0, %1, %2;" : "=r"(ra) : "r"(la), "r"(rk));
    return ra;
}
// Bulk smem->remote-smem copy; one complete_tx (size bytes) at remote mbar.
__device__ __forceinline__ void bulk_cp(uint32_t dst, uint32_t src,
                                        uint32_t bytes, uint32_t rmbar) {
    asm volatile(
        "cp.async.bulk.shared::cluster.shared::cta.mbarrier::complete_tx::bytes "
        "[%0], [%1], %2, [%3];"
        :: "r"(dst), "r"(src), "r"(bytes), "r"(rmbar) : "memory");
}

// ---------------------------------------------------------------------------
// Kernel 1: v_in GEMM.  g_vin[bt][h] = b_in[h] + sum_i x[bt][i] * W_in[h][i]
// ---------------------------------------------------------------------------
#define VIN_SMEM (2*128*132*4)

__global__ __launch_bounds__(256, 1)
void vin_gemm_kernel(const float* __restrict__ x,
                     const float* __restrict__ W_in,
                     const float* __restrict__ b_in) {
    extern __shared__ float sm[];
    float* xs = sm;             // [128 bt][132]
    float* ws = sm + 128*132;   // [128 k][132]

    const int row0 = blockIdx.x * 128;
    const int h0   = blockIdx.y * 128;

    for (int idx = threadIdx.x; idx < 128*32; idx += 256) {
        int r = idx >> 5, c4 = idx & 31;
        float4 v = *(const float4*)(x + (size_t)(row0 + r)*In + c4*4);
        *(float4*)(xs + r*132 + c4*4) = v;
        float4 w = *(const float4*)(W_in + (size_t)(h0 + r)*In + c4*4);
        ws[(c4*4 + 0)*132 + r] = w.x;
        ws[(c4*4 + 1)*132 + r] = w.y;
        ws[(c4*4 + 2)*132 + r] = w.z;
        ws[(c4*4 + 3)*132 + r] = w.w;
    }
    __syncthreads();

    const int ty = threadIdx.x >> 4;
    const int tx = threadIdx.x & 15;
    const int rb = ty * 8;
    const int cb = tx * 8;

    float acc[8][8];
    #pragma unroll
    for (int i = 0; i < 8; i++)
        #pragma unroll
        for (int j = 0; j < 8; j++) acc[i][j] = 0.f;

    #pragma unroll 2
    for (int k = 0; k < 128; ++k) {
        float a[8];
        #pragma unroll
        for (int i = 0; i < 8; i++) a[i] = xs[(rb + i)*132 + k];
        float bb[8];
        *(float4*)(bb)     = *(const float4*)(ws + k*132 + cb);
        *(float4*)(bb + 4) = *(const float4*)(ws + k*132 + cb + 4);
        #pragma unroll
        for (int i = 0; i < 8; i++) {
            float av = a[i];
            #pragma unroll
            for (int j = 0; j < 8; j++) acc[i][j] = fmaf(av, bb[j], acc[i][j]);
        }
    }

    float bias[8];
    *(float4*)(bias)     = *(const float4*)(b_in + h0 + cb);
    *(float4*)(bias + 4) = *(const float4*)(b_in + h0 + cb + 4);

    #pragma unroll
    for (int i = 0; i < 8; i++) {
        float* orow = g_vin + (size_t)(row0 + rb + i)*Hn + h0 + cb;
        float4 o0, o1;
        o0.x = acc[i][0] + bias[0]; o0.y = acc[i][1] + bias[1];
        o0.z = acc[i][2] + bias[2]; o0.w = acc[i][3] + bias[3];
        o1.x = acc[i][4] + bias[4]; o1.y = acc[i][5] + bias[5];
        o1.z = acc[i][6] + bias[6]; o1.w = acc[i][7] + bias[7];
        *(float4*)(orow)     = o0;
        *(float4*)(orow + 4) = o1;
    }
}

// ---------------------------------------------------------------------------
// Kernel 2: recurrence, ONE phase per timestep, BULK fan-out.
// 16 clusters x 8 CTAs, 512 thr. Thread = (hl = tid>>3, seg = tid&7):
// W_hid row (rank*64+hl), cols [seg*64,+64) in regs; j-loop covers all 4
// batches (128 FFMA2). Seg reduction = 3x shfl_xor in the 8-lane group.
// Fresh fr values are STS'd into MY OWN rank block of the write slot, then
// threads 0..6 each issue ONE 1024-B cp.async.bulk of that block to a peer
// CTA (7 arrivals of 1024 B per dest mbar per phase, tx=7168) — replacing
// R12's 2048 scalar st.async whose per-arrival mbar processing dominated.
// Slot layout: [8 srcrank][4 b][64 h] with 1040-B (260-float) block stride:
// j-loop LDS.128 (4-lane broadcast, 8 blocks at 4-bank offsets) conflict-free.
// WAR/exit safety: a peer's bulk ARRIVAL certifies both its prior slot read
// and completion of my earlier bulk's source read; trailing cluster barrier
// covers stragglers' source reads at exit.
// ---------------------------------------------------------------------------
#define BLKW   260                 // floats per rank block (1040 B, 16B mult)
#define BLKB   1024u               // payload bytes per block (4 b * 64 h * 4)
#define SLOTF  (8*BLKW)            // 2080 floats per slot
#define SLOTB  (SLOTF*4)           // 8320 B
#define MB_OFF (2*SLOTB)
#define REC_SMEM (MB_OFF + 64)
#define TXB 7168u                  // 7 remote blocks * 1024 B

struct RState {
    float v[4], vin[4];
    unsigned ovin[4];
    unsigned myot;
    int arr, b2;
};

template<bool SIG>
__device__ __forceinline__ void step_body(
    const float* __restrict__ rbase,   // read slot base
    float* __restrict__ wblk,          // my rank block in write slot (local)
    uint32_t src_u,                    // same block as u32 smem addr
    const uint32_t* __restrict__ dsts, // 7 remote block addrs (write slot)
    const uint32_t* __restrict__ sigs, // 7 remote mbars (write slot)
    const ulonglong2* __restrict__ w,
    int seg, int hl, float al, float oma, float bias,
    RState& S, float* __restrict__ out, bool last)
{
    // j-loop: 4 batches x 64 j (this thread's segment = source block seg)
    const float* fb = rbase + seg*BLKW;
    unsigned long long ae[4] = {0ull,0ull,0ull,0ull};
    unsigned long long ao[4] = {0ull,0ull,0ull,0ull};
    #pragma unroll
    for (int i = 0; i < 16; i++) {
        const ulonglong2 wi = w[i];
        #pragma unroll
        for (int b = 0; b < 4; b++) {
            ulonglong2 f = *(const ulonglong2*)(fb + b*64 + i*4);
            ffma2(ae[b], wi.x, f.x);
            ffma2(ao[b], wi.y, f.y);
        }
    }
    float s0 = hsum2(ae[0]) + hsum2(ao[0]);
    float s1 = hsum2(ae[1]) + hsum2(ao[1]);
    float s2 = hsum2(ae[2]) + hsum2(ao[2]);
    float s3 = hsum2(ae[3]) + hsum2(ao[3]);
    #pragma unroll
    for (int m = 1; m < 8; m <<= 1) {
        s0 += __shfl_xor_sync(0xffffffffu, s0, m);
        s1 += __shfl_xor_sync(0xffffffffu, s1, m);
        s2 += __shfl_xor_sync(0xffffffffu, s2, m);
        s3 += __shfl_xor_sync(0xffffffffu, s3, m);
    }
    float vh[4] = { s0 + bias, s1 + bias, s2 + bias, s3 + bias };
    float fn[4], fr_r[4];
    #pragma unroll
    for (int b = 0; b < 4; b++) {
        float vn = oma*S.v[b] + al*(vh[b] + S.vin[b]);
        float vr = oma*vn + al*vh[b];
        S.v[b] = vn;
        fn[b]   = fmaxf(vn, 0.f);
        fr_r[b] = fmaxf(vr, 0.f);
    }

    if (SIG) {
        // stage fresh values into my own rank block of the write slot
        if (seg < 4) wblk[seg*64 + hl] = fn[seg];
        __syncthreads();
        if (threadIdx.x < 7) {
            asm volatile("fence.proxy.async.shared::cta;" ::: "memory");
            bulk_cp(dsts[threadIdx.x], src_u, BLKB, sigs[threadIdx.x]);
        }
    }

    // one output float per thread; STG + prefetch hide the bulk flight
    out[S.myot] = S.arr ? fr_r[S.b2] : fn[S.b2];
    S.myot += Hn;
    if (!last) {
        #pragma unroll
        for (int b = 0; b < 4; b++) {
            S.ovin[b] += Hn;
            S.vin[b] = __ldg(g_vin + S.ovin[b]);
        }
    }
}

__global__ __launch_bounds__(512, 1) __cluster_dims__(8, 1, 1)
void recur_kernel(const float* __restrict__ init_state,
                  const float* __restrict__ W_hid,
                  const float* __restrict__ b_hid,
                  const float* __restrict__ alpha,
                  float* __restrict__ out) {
    extern __shared__ float sm[];
    float* fr0 = sm;             // slot0: [8 srcrank][4 b][64] stride 260
    float* fr1 = sm + SLOTF;

    const int tid  = threadIdx.x;
    const int rank = blockIdx.x;      // cluster rank -> h slice & my block
    const int clu  = blockIdx.y;
    const int hl   = tid >> 3;        // 0..63
    const int seg  = tid & 7;         // j segment == source rank block

    const uint32_t smb = smem_u32(sm);
    const uint32_t mb0 = smb + MB_OFF;
    const uint32_t mb1 = mb0 + 16;

    // ---- W_hid slice into regs (row rank*64+hl, cols seg*64..+64) ----
    ulonglong2 w[16];
    {
        const float* wr = W_hid + (size_t)(rank*64 + hl)*Hn + seg*64;
        #pragma unroll
        for (int i = 0; i < 16; i++)
            w[i] = *(const ulonglong2*)(wr + i*4);
    }

    // ---- fill slot0 (all 8 blocks) with relu(init_state) ----
    for (int idx = tid; idx < 2048; idx += 512) {
        int k = idx >> 8;            // source rank block
        int b = (idx >> 6) & 3;
        int i = idx & 63;
        float s = fmaxf(init_state[(size_t)(clu*4 + b)*Hn + k*64 + i], 0.f);
        fr0[k*BLKW + b*64 + i] = s;
    }

    // ---- mbarrier init + prologue arm ----
    if (tid == 0) {
        mbar_init(mb0, 1); mbar_init(mb1, 1);
        asm volatile("fence.mbarrier_init.release.cluster;" ::: "memory");
        mbar_expect_tx(mb0, TXB);
        mbar_expect_tx(mb1, TXB);
    }

    // ---- per-thread state ----
    const int hg = rank*64 + hl;
    const float al   = alpha[hg];
    const float oma  = 1.f - al;
    const float bias = b_hid[hg];
    RState S;
    S.arr = seg >> 2;
    S.b2  = seg & 3;
    #pragma unroll
    for (int b = 0; b < 4; b++) {
        const int bg = clu*4 + b;
        S.v[b]    = init_state[(size_t)bg*Hn + hg];
        S.ovin[b] = (unsigned)(bg*TnHn + hg);
        S.vin[b]  = __ldg(g_vin + S.ovin[b]);
    }
    S.myot = (unsigned)(S.arr*BTH) + (unsigned)((clu*4 + S.b2)*TnHn + hg);

    // ---- loop-invariant bulk targets: my rank block in each peer, per slot.
    //      Thread k (0..6) targets dest rank (rank+1+k)&7. ----
    const uint32_t myblk0_u = smb + (uint32_t)(rank*BLKW)*4u;
    const uint32_t myblk1_u = myblk0_u + SLOTB;
    uint32_t dst0[7], dst1[7], sg0[7], sg1[7];
    #pragma unroll
    for (int k = 0; k < 7; k++) {
        int dr = (rank + 1 + k) & 7;
        dst0[k] = mapa_rk(myblk0_u, dr);
        dst1[k] = mapa_rk(myblk1_u, dr);
        sg0[k]  = mapa_rk(mb0, dr);
        sg1[k]  = mapa_rk(mb1, dr);
    }
    float* wblk0 = fr0 + rank*BLKW;
    float* wblk1 = fr1 + rank*BLKW;

    __syncthreads();
    asm volatile("barrier.cluster.arrive.aligned;" ::: "memory");
    asm volatile("barrier.cluster.wait.aligned;"   ::: "memory");

    // ---- t = 0: read slot0 (prologue-filled), write slot1 ----
    step_body<true>(fr0, wblk1, myblk1_u, dst1, sg1, w, seg, hl,
                    al, oma, bias, S, out, false);

    // ---- t = 2u+1 (read slot1, write slot0), t = 2u+2 (read 0, write 1) ----
    #pragma unroll 1
    for (int u = 0; u < 255; ++u) {
        const uint32_t par = (uint32_t)(u & 1);
        mbar_wait(mb1, par);
        if (tid == 0) mbar_expect_tx(mb1, TXB);
        step_body<true>(fr1, wblk0, myblk0_u, dst0, sg0, w, seg, hl,
                        al, oma, bias, S, out, false);

        mbar_wait(mb0, par);
        if (tid == 0) mbar_expect_tx(mb0, TXB);
        step_body<true>(fr0, wblk1, myblk1_u, dst1, sg1, w, seg, hl,
                        al, oma, bias, S, out, false);
    }

    // ---- t = 511: read slot1, no fan-out, no prefetch ----
    mbar_wait(mb1, 1u);
    step_body<false>(fr1, wblk0, myblk0_u, dst0, sg0, w, seg, hl,
                     al, oma, bias, S, out, true);

    // Keep all smem alive until every CTA's last bulks (and their source
    // reads) are globally complete.
    asm volatile("barrier.cluster.arrive.aligned;" ::: "memory");
    asm volatile("barrier.cluster.wait.aligned;"   ::: "memory");
}

// ---------------------------------------------------------------------------
extern "C" void kernel_launch(void* const* d_in, const int* in_sizes, int n_in,
                              void* d_out, int out_size) {
    const float* x          = (const float*)d_in[0];
    const float* init_state = (const float*)d_in[1];
    const float* W_in       = (const float*)d_in[2];
    const float* b_in       = (const float*)d_in[3];
    const float* W_hid      = (const float*)d_in[4];
    const float* b_hid      = (const float*)d_in[5];
    const float* alpha      = (const float*)d_in[6];
    float* out = (float*)d_out;

    cudaFuncSetAttribute(vin_gemm_kernel,
                         cudaFuncAttributeMaxDynamicSharedMemorySize, VIN_SMEM);
    cudaFuncSetAttribute(recur_kernel,
                         cudaFuncAttributeMaxDynamicSharedMemorySize, REC_SMEM);

    vin_gemm_kernel<<<dim3(Bn*Tn/128, Hn/128), 256, VIN_SMEM>>>(x, W_in, b_in);
    recur_kernel<<<dim3(8, Bn/4), 512, REC_SMEM>>>(init_state, W_hid, b_hid,
                                                   alpha, out);
}

// round 16
// speedup vs baseline: 1.6890x; 1.6465x over previous
#include <cuda_runtime.h>
#include <cstdint>

#define Bn 64
#define Tn 512
#define In 128
#define Hn 512
#define TnHn (Tn*Hn)
#define BTH (64*512*512)

// 64MB scratch for precomputed v_in = x @ W_in^T + b_in, layout [B*T, H]
__device__ float g_vin[BTH];

__device__ __forceinline__ uint32_t smem_u32(const void* p) {
    return (uint32_t)__cvta_generic_to_shared(p);
}

// Packed fp32x2 FMA (Blackwell FFMA2): d = a*b + d on both lanes, exact fp32.
__device__ __forceinline__ void ffma2(unsigned long long& d,
                                      unsigned long long a,
                                      unsigned long long b) {
    asm("fma.rn.f32x2 %0, %1, %2, %0;" : "+l"(d) : "l"(a), "l"(b));
}
__device__ __forceinline__ float hsum2(unsigned long long a) {
    float lo, hi;
    asm("mov.b64 {%0, %1}, %2;" : "=f"(lo), "=f"(hi) : "l"(a));
    return lo + hi;
}

__device__ __forceinline__ void mbar_init(uint32_t mbar, uint32_t cnt) {
    asm volatile("mbarrier.init.shared.b64 [%0], %1;" :: "r"(mbar), "r"(cnt) : "memory");
}
__device__ __forceinline__ void mbar_expect_tx(uint32_t mbar, uint32_t bytes) {
    asm volatile("mbarrier.arrive.expect_tx.shared.b64 _, [%0], %1;"
                 :: "r"(mbar), "r"(bytes) : "memory");
}
__device__ __forceinline__ void mbar_wait(uint32_t mbar, uint32_t parity) {
    asm volatile(
        "{\n\t.reg .pred P;\n\t"
        "WL_%=:\n\t"
        "mbarrier.try_wait.parity.acquire.cta.shared::cta.b64 P, [%0], %1, 0x989680;\n\t"
        "@!P bra WL_%=;\n\t}"
        :: "r"(mbar), "r"(parity) : "memory");
}
__device__ __forceinline__ uint32_t mapa_rk(uint32_t la, int rk) {
    uint32_t ra;
    asm("mapa.shared::cluster.u32 %0, %1, %2;" : "=r"(ra) : "r"(la), "r"(rk));
    return ra;
}
// Remote smem store that also delivers complete_tx to the remote mbarrier.
__device__ __forceinline__ void st_async_f32(uint32_t raddr, float v, uint32_t rmbar) {
    asm volatile("st.async.shared::cluster.mbarrier::complete_tx::bytes.f32 [%0], %1, [%2];"
                 :: "r"(raddr), "f"(v), "r"(rmbar) : "memory");
}

// ---------------------------------------------------------------------------
// Kernel 1: v_in GEMM.  g_vin[bt][h] = b_in[h] + sum_i x[bt][i] * W_in[h][i]
// ---------------------------------------------------------------------------
#define VIN_SMEM (2*128*132*4)

__global__ __launch_bounds__(256, 1)
void vin_gemm_kernel(const float* __restrict__ x,
                     const float* __restrict__ W_in,
                     const float* __restrict__ b_in) {
    extern __shared__ float sm[];
    float* xs = sm;             // [128 bt][132]
    float* ws = sm + 128*132;   // [128 k][132]

    const int row0 = blockIdx.x * 128;
    const int h0   = blockIdx.y * 128;

    for (int idx = threadIdx.x; idx < 128*32; idx += 256) {
        int r = idx >> 5, c4 = idx & 31;
        float4 v = *(const float4*)(x + (size_t)(row0 + r)*In + c4*4);
        *(float4*)(xs + r*132 + c4*4) = v;
        float4 w = *(const float4*)(W_in + (size_t)(h0 + r)*In + c4*4);
        ws[(c4*4 + 0)*132 + r] = w.x;
        ws[(c4*4 + 1)*132 + r] = w.y;
        ws[(c4*4 + 2)*132 + r] = w.z;
        ws[(c4*4 + 3)*132 + r] = w.w;
    }
    __syncthreads();

    const int ty = threadIdx.x >> 4;
    const int tx = threadIdx.x & 15;
    const int rb = ty * 8;
    const int cb = tx * 8;

    float acc[8][8];
    #pragma unroll
    for (int i = 0; i < 8; i++)
        #pragma unroll
        for (int j = 0; j < 8; j++) acc[i][j] = 0.f;

    #pragma unroll 2
    for (int k = 0; k < 128; ++k) {
        float a[8];
        #pragma unroll
        for (int i = 0; i < 8; i++) a[i] = xs[(rb + i)*132 + k];
        float bb[8];
        *(float4*)(bb)     = *(const float4*)(ws + k*132 + cb);
        *(float4*)(bb + 4) = *(const float4*)(ws + k*132 + cb + 4);
        #pragma unroll
        for (int i = 0; i < 8; i++) {
            float av = a[i];
            #pragma unroll
            for (int j = 0; j < 8; j++) acc[i][j] = fmaf(av, bb[j], acc[i][j]);
        }
    }

    float bias[8];
    *(float4*)(bias)     = *(const float4*)(b_in + h0 + cb);
    *(float4*)(bias + 4) = *(const float4*)(b_in + h0 + cb + 4);

    #pragma unroll
    for (int i = 0; i < 8; i++) {
        float* orow = g_vin + (size_t)(row0 + rb + i)*Hn + h0 + cb;
        float4 o0, o1;
        o0.x = acc[i][0] + bias[0]; o0.y = acc[i][1] + bias[1];
        o0.z = acc[i][2] + bias[2]; o0.w = acc[i][3] + bias[3];
        o1.x = acc[i][4] + bias[4]; o1.y = acc[i][5] + bias[5];
        o1.z = acc[i][6] + bias[6]; o1.w = acc[i][7] + bias[7];
        *(float4*)(orow)     = o0;
        *(float4*)(orow + 4) = o1;
    }
}

// ---------------------------------------------------------------------------
// Kernel 2: recurrence. 32 clusters x 8 CTAs x 256 thr, 2 CTAs/SM
// (different clusters co-resident -> one cluster's wait hides under the
// other's compute). Cluster owns batches {2c, 2c+1}: group A / group B
// ping-pong on separate mbar pairs (the R9 overlap structure).
// Thread = (hl = tid>>2, sg = tid&3): W_hid row (rank*64+hl),
// cols [sg*128,+128) in 64 regs. Phase = one (group, timestep):
//   wait mbar (peeled for t=0) -> 64 FFMA2 + 32 broadcast LDS.128
//   -> 2x shfl_xor over the 4 sg lanes -> replicated ew update
//   -> 2 st.async (dest ranks 2sg, 2sg+1) -> (sg<2) 1 STG -> vin prefetch.
// No __syncthreads in the loop: per-thread read->value->st.async dependence
// gives WAR safety (R12-verified); tid0's own stores gate remote progress
// past its expect_tx re-arm. tx per dest mbar per phase = 8 src ranks *
// 64 h * 4 B = 2048 B.
// fr layout per group per slot: [4 sg][132] pad -> conflict-free broadcast.
// ---------------------------------------------------------------------------
#define SEGW2  132
#define GSLOT  (4*SEGW2)            // 528 floats per slot
#define GRPF   (2*GSLOT)            // 1056 floats per group (2 slots)
#define MB_OFF (2*GRPF*4)           // 8448 B
#define REC_SMEM (MB_OFF + 64)
#define TXB 2048u

template<bool SIG>
__device__ __forceinline__ void phase(
    const float* __restrict__ fb,      // read base: group slot + sg*132
    uint32_t dst0, uint32_t dst1,      // remote fr addrs in write slot
    uint32_t sig0, uint32_t sig1,      // remote mbars for write slot
    const ulonglong2* __restrict__ w,
    float al, float oma, float bias, int sg,
    float& v, float& vin, unsigned& ovin, unsigned& myot,
    float* __restrict__ out, bool last)
{
    unsigned long long a0 = 0ull, a1 = 0ull, a2 = 0ull, a3 = 0ull;
    #pragma unroll
    for (int i = 0; i < 16; i++) {
        ulonglong2 f0 = *(const ulonglong2*)(fb + i*8);
        ulonglong2 f1 = *(const ulonglong2*)(fb + i*8 + 4);
        ffma2(a0, w[2*i].x,   f0.x);
        ffma2(a1, w[2*i].y,   f0.y);
        ffma2(a2, w[2*i+1].x, f1.x);
        ffma2(a3, w[2*i+1].y, f1.y);
    }
    float s = (hsum2(a0) + hsum2(a1)) + (hsum2(a2) + hsum2(a3));
    s += __shfl_xor_sync(0xffffffffu, s, 1);
    s += __shfl_xor_sync(0xffffffffu, s, 2);

    float vh = s + bias;
    float vn = oma*v + al*(vh + vin);
    float vr = oma*vn + al*vh;
    v = vn;
    float fn = fmaxf(vn, 0.f);

    if (SIG) {
        st_async_f32(dst0, fn, sig0);
        st_async_f32(dst1, fn, sig1);
    }
    if (sg < 2) out[myot] = sg ? fmaxf(vr, 0.f) : fn;
    myot += Hn;
    if (!last) { ovin += Hn; vin = __ldg(g_vin + ovin); }
}

__global__ __launch_bounds__(256, 2) __cluster_dims__(8, 1, 1)
void recur_kernel(const float* __restrict__ init_state,
                  const float* __restrict__ W_hid,
                  const float* __restrict__ b_hid,
                  const float* __restrict__ alpha,
                  float* __restrict__ out) {
    extern __shared__ float sm[];
    float* frA = sm;             // group A: [2 slot][4 sg][132]
    float* frB = sm + GRPF;

    const int tid  = threadIdx.x;
    const int rank = blockIdx.x;      // cluster rank -> h slice
    const int clu  = blockIdx.y;      // 0..31 -> batches {2clu, 2clu+1}
    const int hl   = tid >> 2;        // 0..63
    const int sg   = tid & 3;         // j segment (128 wide)

    const uint32_t smb = smem_u32(sm);
    const uint32_t mbA0 = smb + MB_OFF;
    const uint32_t mbA1 = mbA0 + 8;
    const uint32_t mbB0 = mbA0 + 16;
    const uint32_t mbB1 = mbA0 + 24;

    // ---- W_hid slice: row rank*64+hl, cols [sg*128, +128) -> 64 regs ----
    ulonglong2 w[32];
    {
        const float* wr = W_hid + (size_t)(rank*64 + hl)*Hn + sg*128;
        #pragma unroll
        for (int i = 0; i < 32; i++)
            w[i] = *(const ulonglong2*)(wr + i*4);
    }

    // ---- fill slot0 of both groups with relu(init_state) ----
    for (int idx = tid; idx < 2*512; idx += 256) {
        int g = idx >> 9, j = idx & 511;
        float s = fmaxf(init_state[(size_t)(clu*2 + g)*Hn + j], 0.f);
        float* dst = (g ? frB : frA) + (j >> 7)*SEGW2 + (j & 127);
        *dst = s;
    }

    // ---- mbarrier init + prologue arm ----
    if (tid == 0) {
        mbar_init(mbA0, 1); mbar_init(mbA1, 1);
        mbar_init(mbB0, 1); mbar_init(mbB1, 1);
        asm volatile("fence.mbarrier_init.release.cluster;" ::: "memory");
        mbar_expect_tx(mbA0, TXB); mbar_expect_tx(mbA1, TXB);
        mbar_expect_tx(mbB0, TXB); mbar_expect_tx(mbB1, TXB);
    }

    // ---- per-thread recurrence state ----
    const int hg = rank*64 + hl;
    const float al   = alpha[hg];
    const float oma  = 1.f - al;
    const float bias = b_hid[hg];
    const int bA = clu*2, bB = clu*2 + 1;
    float vA = init_state[(size_t)bA*Hn + hg];
    float vB = init_state[(size_t)bB*Hn + hg];
    unsigned ovA = (unsigned)(bA*TnHn + hg);
    unsigned ovB = (unsigned)(bB*TnHn + hg);
    float vinA = __ldg(g_vin + ovA);
    float vinB = __ldg(g_vin + ovB);
    // output stream: sg 0 -> states, sg 1 -> relax (per group)
    unsigned moA = (unsigned)((sg & 1)*BTH) + (unsigned)(bA*TnHn + hg);
    unsigned moB = (unsigned)((sg & 1)*BTH) + (unsigned)(bB*TnHn + hg);

    // ---- loop-invariant remote addresses: my h lands at padded offset ----
    const uint32_t doff = (uint32_t)((hg >> 7)*SEGW2 + (hg & 127)) * 4u;
    const int d0 = 2*sg, d1 = 2*sg + 1;
    const uint32_t A0d0 = mapa_rk(smb + doff,                          d0);
    const uint32_t A0d1 = mapa_rk(smb + doff,                          d1);
    const uint32_t A1d0 = mapa_rk(smb + GSLOT*4u + doff,               d0);
    const uint32_t A1d1 = mapa_rk(smb + GSLOT*4u + doff,               d1);
    const uint32_t B0d0 = mapa_rk(smb + GRPF*4u + doff,                d0);
    const uint32_t B0d1 = mapa_rk(smb + GRPF*4u + doff,                d1);
    const uint32_t B1d0 = mapa_rk(smb + GRPF*4u + GSLOT*4u + doff,     d0);
    const uint32_t B1d1 = mapa_rk(smb + GRPF*4u + GSLOT*4u + doff,     d1);
    const uint32_t sA0d0 = mapa_rk(mbA0, d0), sA0d1 = mapa_rk(mbA0, d1);
    const uint32_t sA1d0 = mapa_rk(mbA1, d0), sA1d1 = mapa_rk(mbA1, d1);
    const uint32_t sB0d0 = mapa_rk(mbB0, d0), sB0d1 = mapa_rk(mbB0, d1);
    const uint32_t sB1d0 = mapa_rk(mbB1, d0), sB1d1 = mapa_rk(mbB1, d1);

    const float* fA0 = frA + sg*SEGW2;            // slot0 read base
    const float* fA1 = frA + GSLOT + sg*SEGW2;    // slot1 read base
    const float* fB0 = frB + sg*SEGW2;
    const float* fB1 = frB + GSLOT + sg*SEGW2;

    __syncthreads();
    asm volatile("barrier.cluster.arrive.aligned;" ::: "memory");
    asm volatile("barrier.cluster.wait.aligned;"   ::: "memory");

    // ---- t = 0: read slot0 (prologue), write slot1, no wait ----
    phase<true>(fA0, A1d0, A1d1, sA1d0, sA1d1, w, al, oma, bias, sg,
                vA, vinA, ovA, moA, out, false);
    phase<true>(fB0, B1d0, B1d1, sB1d0, sB1d1, w, al, oma, bias, sg,
                vB, vinB, ovB, moB, out, false);

    // ---- steady state: u covers t=2u+1 (slot1->0) and t=2u+2 (slot0->1) ----
    #pragma unroll 1
    for (int u = 0; u < 255; ++u) {
        const uint32_t par = (uint32_t)(u & 1);

        mbar_wait(mbA1, par);
        if (tid == 0) mbar_expect_tx(mbA1, TXB);
        phase<true>(fA1, A0d0, A0d1, sA0d0, sA0d1, w, al, oma, bias, sg,
                    vA, vinA, ovA, moA, out, false);
        mbar_wait(mbB1, par);
        if (tid == 0) mbar_expect_tx(mbB1, TXB);
        phase<true>(fB1, B0d0, B0d1, sB0d0, sB0d1, w, al, oma, bias, sg,
                    vB, vinB, ovB, moB, out, false);

        mbar_wait(mbA0, par);
        if (tid == 0) mbar_expect_tx(mbA0, TXB);
        phase<true>(fA0, A1d0, A1d1, sA1d0, sA1d1, w, al, oma, bias, sg,
                    vA, vinA, ovA, moA, out, false);
        mbar_wait(mbB0, par);
        if (tid == 0) mbar_expect_tx(mbB0, TXB);
        phase<true>(fB0, B1d0, B1d1, sB1d0, sB1d1, w, al, oma, bias, sg,
                    vB, vinB, ovB, moB, out, false);
    }

    // ---- t = 511: read slot1, no fan-out, no prefetch (t+1 == Tn) ----
    mbar_wait(mbA1, 1u);
    phase<false>(fA1, A0d0, A0d1, sA0d0, sA0d1, w, al, oma, bias, sg,
                 vA, vinA, ovA, moA, out, true);
    mbar_wait(mbB1, 1u);
    phase<false>(fB1, B0d0, B0d1, sB0d0, sB0d1, w, al, oma, bias, sg,
                 vB, vinB, ovB, moB, out, true);

    // No CTA may exit while a peer could still have remote stores in flight
    // toward its smem (exit deallocates smem -> fault).
    asm volatile("barrier.cluster.arrive.aligned;" ::: "memory");
    asm volatile("barrier.cluster.wait.aligned;"   ::: "memory");
}

// ---------------------------------------------------------------------------
extern "C" void kernel_launch(void* const* d_in, const int* in_sizes, int n_in,
                              void* d_out, int out_size) {
    const float* x          = (const float*)d_in[0];
    const float* init_state = (const float*)d_in[1];
    const float* W_in       = (const float*)d_in[2];
    const float* b_in       = (const float*)d_in[3];
    const float* W_hid      = (const float*)d_in[4];
    const float* b_hid      = (const float*)d_in[5];
    const float* alpha      = (const float*)d_in[6];
    float* out = (float*)d_out;

    cudaFuncSetAttribute(vin_gemm_kernel,
                         cudaFuncAttributeMaxDynamicSharedMemorySize, VIN_SMEM);
    cudaFuncSetAttribute(recur_kernel,
                         cudaFuncAttributeMaxDynamicSharedMemorySize, REC_SMEM);

    vin_gemm_kernel<<<dim3(Bn*Tn/128, Hn/128), 256, VIN_SMEM>>>(x, W_in, b_in);
    recur_kernel<<<dim3(8, Bn/2), 256, REC_SMEM>>>(init_state, W_hid, b_hid,
                                                   alpha, out);
}